// round 3
// baseline (speedup 1.0000x reference)
#include <cuda_runtime.h>
#include <cstddef>

// SpecialFlatten == batched float2 transpose: in2 [B, R, CP] -> out2 [B, CP, R]
// B=32, R=2048, C=512, CP=256. float4 on both GMEM sides, streaming cache hints.
//
// Tile: 128 R-rows x 32 CP-cols (float2 units), 512 threads.
// Smem even/odd row planes + permuted column layout => all STS.64/LDS.64
// lane-linear, zero bank conflicts (same scheme as R2, scaled to 64 pairs).

namespace {
constexpr int B   = 32;
constexpr int R   = 2048;
constexpr int CP  = 256;           // float2 columns
constexpr int C4  = CP / 2;        // 128 float4 per input row
constexpr int R4  = R / 2;         // 1024 float4 per output row
constexpr int TILE_R = 128;        // float2 rows per tile
constexpr int TILE_C = 32;         // float2 cols per tile (= 16 float4)
constexpr int NPAIR  = TILE_R / 2; // 64 row pairs
}

__global__ __launch_bounds__(512)
void special_flatten_v5(const float4* __restrict__ in,
                        float4* __restrict__ out) {
    __shared__ float2 sA[NPAIR][33];   // even rows (row 2m -> sA[m])
    __shared__ float2 sB[NPAIR][33];   // odd rows  (row 2m+1 -> sB[m])

    const int b = blockIdx.z;
    const float4* __restrict__ inb  = in  + (size_t)b * R * C4;
    float4* __restrict__       outb = out + (size_t)b * CP * R4;

    const int tid = threadIdx.x;

    // ---- Load phase: 4x LDG.128 (streaming) per thread, STS.64 lane-linear ----
    {
        const int tx = tid & 15;                 // float4 col within tile (0..15)
        const int ty = tid >> 4;                 // 0..31
        const int c4 = blockIdx.x * (TILE_C / 2) + tx;
        const int r0 = blockIdx.y * TILE_R;
#pragma unroll
        for (int k = 0; k < 2; k++) {
            const int m = ty + 32 * k;           // row pair 0..63
            const float4 v0 = __ldcs(&inb[(size_t)(r0 + 2 * m    ) * C4 + c4]);
            const float4 v1 = __ldcs(&inb[(size_t)(r0 + 2 * m + 1) * C4 + c4]);
            // logical cols 2tx, 2tx+1 -> storage cols tx, tx+16 (permuted)
            sA[m][tx]      = make_float2(v0.x, v0.y);
            sA[m][tx + 16] = make_float2(v0.z, v0.w);
            sB[m][tx]      = make_float2(v1.x, v1.y);
            sB[m][tx + 16] = make_float2(v1.z, v1.w);
        }
    }

    __syncthreads();

    // ---- Store phase: LDS.64 lane-linear, 4x STG.128 (streaming) per thread ----
    {
        const int sx = tid & 63;                 // float4 R-index within tile (0..63)
        const int sy = tid >> 6;                 // 0..7
        const int r4 = blockIdx.y * (TILE_R / 2) + sx;
#pragma unroll
        for (int n = 0; n < 4; n++) {
            const int c  = sy + 8 * n;           // CP-local col 0..31
            const int sc = (c >> 1) + (c & 1) * 16;   // permuted storage col
            const float2 a  = sA[sx][sc];        // in2[2*sx][c]
            const float2 bb = sB[sx][sc];        // in2[2*sx+1][c]
            __stcs(&outb[(size_t)(blockIdx.x * TILE_C + c) * R4 + r4],
                   make_float4(a.x, a.y, bb.x, bb.y));
        }
    }
}

extern "C" void kernel_launch(void* const* d_in, const int* in_sizes, int n_in,
                              void* d_out, int out_size) {
    const float4* in  = (const float4*)d_in[0];
    float4*       out = (float4*)d_out;

    dim3 block(512, 1, 1);
    dim3 grid(CP / TILE_C, R / TILE_R, B);   // (8, 16, 32) = 4096 blocks
    special_flatten_v5<<<grid, block>>>(in, out);
}

// round 4
// speedup vs baseline: 1.1934x; 1.1934x over previous
#include <cuda_runtime.h>
#include <cstddef>

// SpecialFlatten == batched float2 transpose: in2 [B, R, CP] -> out2 [B, CP, R]
// B=32, R=2048, C=512, CP=256. Fully float4-vectorized, NO cache hints
// (R3 showed .cs hints regress DRAM efficiency on this part).
//
// Identical to the proven R2 kernel (64R x 32CP tile, 256 threads, even/odd
// smem planes + permuted columns, zero bank conflicts) with ONE change:
// blockIdx.x now walks R-tiles fastest so consecutively-scheduled CTAs write
// adjacent 256B chunks of the same output rows (better DRAM write locality).

namespace {
constexpr int B   = 32;
constexpr int R   = 2048;
constexpr int CP  = 256;           // float2 columns
constexpr int C4  = CP / 2;        // 128 float4 per input row
constexpr int R4  = R / 2;         // 1024 float4 per output row
constexpr int TILE_R = 64;         // float2 rows per tile
constexpr int TILE_C = 32;         // float2 cols per tile (= 16 float4)
}

__global__ __launch_bounds__(256)
void special_flatten_v6(const float4* __restrict__ in,
                        float4* __restrict__ out) {
    __shared__ float2 sA[32][33];   // even rows of the tile (row 2m -> sA[m])
    __shared__ float2 sB[32][33];   // odd rows  (row 2m+1 -> sB[m])

    const int b = blockIdx.z;
    const float4* __restrict__ inb  = in  + (size_t)b * R * C4;
    float4* __restrict__       outb = out + (size_t)b * CP * R4;

    const int tid   = threadIdx.x;
    const int rtile = blockIdx.x;   // R-tile index (fastest-varying)
    const int ctile = blockIdx.y;   // CP-tile index

    // ---- Load phase: 4x LDG.128 per thread, STS.64 lane-linear ----
    {
        const int tx = tid & 15;                 // float4 col within tile (0..15)
        const int ty = tid >> 4;                 // 0..15
        const int c4 = ctile * (TILE_C / 2) + tx;
        const int r0 = rtile * TILE_R;
#pragma unroll
        for (int k = 0; k < 2; k++) {
            const int m = ty + 16 * k;           // row pair 0..31
            const float4 v0 = inb[(size_t)(r0 + 2 * m    ) * C4 + c4];
            const float4 v1 = inb[(size_t)(r0 + 2 * m + 1) * C4 + c4];
            // logical cols 2tx, 2tx+1 -> storage cols tx, tx+16 (permuted)
            sA[m][tx]      = make_float2(v0.x, v0.y);
            sA[m][tx + 16] = make_float2(v0.z, v0.w);
            sB[m][tx]      = make_float2(v1.x, v1.y);
            sB[m][tx + 16] = make_float2(v1.z, v1.w);
        }
    }

    __syncthreads();

    // ---- Store phase: LDS.64 lane-linear, 4x STG.128 per thread ----
    {
        const int sx = tid & 31;                 // float4 R-index within tile (0..31)
        const int sy = tid >> 5;                 // 0..7
        const int r4 = rtile * (TILE_R / 2) + sx;
#pragma unroll
        for (int n = 0; n < 4; n++) {
            const int c  = sy + 8 * n;           // CP-local col 0..31
            const int sc = (c >> 1) + (c & 1) * 16;   // permuted storage col
            const float2 a  = sA[sx][sc];        // in2[2*sx][c]
            const float2 bb = sB[sx][sc];        // in2[2*sx+1][c]
            outb[(size_t)(ctile * TILE_C + c) * R4 + r4] =
                make_float4(a.x, a.y, bb.x, bb.y);
        }
    }
}

extern "C" void kernel_launch(void* const* d_in, const int* in_sizes, int n_in,
                              void* d_out, int out_size) {
    const float4* in  = (const float4*)d_in[0];
    float4*       out = (float4*)d_out;

    dim3 block(256, 1, 1);
    dim3 grid(R / TILE_R, CP / TILE_C, B);   // (32, 8, 32) = 8192 blocks
    special_flatten_v6<<<grid, block>>>(in, out);
}